// round 6
// baseline (speedup 1.0000x reference)
#include <cuda_runtime.h>
#include <cuda_bf16.h>
#include <cstdint>

// ---------------------------------------------------------------------------
// MultiPathLayer: N=50000 nodes, E=800000 edges, D=128.
// GEMMs via mma.sync bf16 (split-bf16, fp32 accuracy), ldmatrix, cp.async
// (hi/lo pipelined), smem chain-fusion. Edge phase via CSR-by-dst:
// warp-per-node register accumulation — no atomics, no dst gathers.
// ---------------------------------------------------------------------------

#define NMAX 50000
#define EMAX 800000
#define DDIM 128
#define WPAD 136           // padded row length in bf16 elems — LDSM conflict-free
#define WELEMS (128 * WPAD)

__device__ float4 g_b0 [NMAX * 32];   // Un   -> later E0
__device__ float4 g_b1 [NMAX * 32];   // Vn   -> later E1
__device__ float4 g_b2 [NMAX * 32];   // Ue   -> later E2
__device__ float4 g_b3 [NMAX * 32];   // Ve   -> later Att
__device__ float4 g_b4 [NMAX * 32];   // Hagg
__device__ float4 g_b5 [NMAX * 32];   // Einit
__device__ float4 g_b6 [NMAX * 32];   // Pn
__device__ float4 g_b7 [NMAX * 32];   // Pe
__device__ float4 g_b8 [NMAX * 32];   // T
__device__ float4 g_b9 [NMAX * 32];   // Fn
__device__ float4 g_b10[NMAX * 32];   // Fe
__device__ float4 g_b11[NMAX * 32];   // Qp
__device__ float4 g_b13[NMAX * 32];   // Fs
__device__ float  g_s[NMAX];
__device__ float  g_deg[NMAX];
__device__ float  g_bnsum[DDIM];
__device__ float  g_bnsq[DDIM];

// CSR-by-dst structures
__device__ int   g_cnt[NMAX];
__device__ int   g_cnt2[NMAX];
__device__ int   g_rowptr[NMAX + 1];
__device__ int   g_perm[EMAX];     // src node per CSR slot
__device__ float g_normArr[EMAX];  // conv_w[bt]+conv_b per CSR slot
__device__ float g_d2Arr[EMAX];    // squared distance per CSR slot

// Pre-converted weights: [weight][hi/lo][n*WPAD + k] (B operand layout [n][k]).
__device__ __align__(16) __nv_bfloat16 g_wt[18][2][WELEMS];

__device__ __forceinline__ float mishf(float x) {
    float e  = __expf(fminf(x, 30.0f));
    float t  = 1.0f + e;
    float t2 = t * t;
    return x * __fdividef(t2 - 1.0f, t2 + 1.0f);
}

__device__ __forceinline__ uint32_t smem_u32(const void* p) {
    uint32_t a;
    asm("{ .reg .u64 t; cvta.to.shared.u64 t, %1; cvt.u32.u64 %0, t; }"
        : "=r"(a) : "l"(p));
    return a;
}

__device__ __forceinline__ void mma_bf16(float* c, const uint32_t* a,
                                         const uint32_t* b) {
    asm volatile(
        "mma.sync.aligned.m16n8k16.row.col.f32.bf16.bf16.f32 "
        "{%0,%1,%2,%3}, {%4,%5,%6,%7}, {%8,%9}, {%0,%1,%2,%3};"
        : "+f"(c[0]), "+f"(c[1]), "+f"(c[2]), "+f"(c[3])
        : "r"(a[0]), "r"(a[1]), "r"(a[2]), "r"(a[3]), "r"(b[0]), "r"(b[1]));
}

__device__ __forceinline__ void ldsm4(uint32_t* r, uint32_t addr) {
    asm volatile("ldmatrix.sync.aligned.m8n8.x4.shared.b16 {%0,%1,%2,%3}, [%4];"
        : "=r"(r[0]), "=r"(r[1]), "=r"(r[2]), "=r"(r[3]) : "r"(addr));
}

__device__ __forceinline__ void cp_async16(uint32_t saddr, const void* g) {
    asm volatile("cp.async.cg.shared.global [%0], [%1], 16;"
                 :: "r"(saddr), "l"(g) : "memory");
}

// ---------------------------------------------------------------------------
// Weight setup.
// ---------------------------------------------------------------------------
struct WPtrs { const float* p[18]; };

__global__ void setup_weights(WPtrs wp)
{
    int w = blockIdx.x;
    const float* W = wp.p[w];
    __nv_bfloat16* hi = g_wt[w][0];
    __nv_bfloat16* lo = g_wt[w][1];
    for (int it = 0; it < 8; ++it) {
        int idx = blockIdx.y * 2048 + it * 256 + threadIdx.x;
        int k = idx >> 7;
        int n = idx & 127;
        float v = W[idx];
        __nv_bfloat16 h = __float2bfloat16(v);
        __nv_bfloat16 l = __float2bfloat16(v - __bfloat162float(h));
        hi[n * WPAD + k] = h;
        lo[n * WPAD + k] = l;
    }
}

// ---------------------------------------------------------------------------
// CSR build: count -> scan -> scatter
// ---------------------------------------------------------------------------
__global__ void csr_count(const int* __restrict__ ei, int E)
{
    int e = blockIdx.x * 256 + threadIdx.x;
    if (e >= E) return;
    atomicAdd(&g_cnt[ei[E + e]], 1);
}

__global__ void __launch_bounds__(1024) csr_scan(int n)
{
    __shared__ int sdata[1024];
    int t = threadIdx.x;
    int chunk = (n + 1023) >> 10;
    int start = t * chunk;
    int end = min(start + chunk, n);
    int s = 0;
    for (int i = start; i < end; ++i) s += g_cnt[i];
    sdata[t] = s;
    __syncthreads();
    // inclusive Hillis-Steele scan
    for (int off = 1; off < 1024; off <<= 1) {
        int v = (t >= off) ? sdata[t - off] : 0;
        __syncthreads();
        sdata[t] += v;
        __syncthreads();
    }
    int prefix = (t == 0) ? 0 : sdata[t - 1];
    for (int i = start; i < end; ++i) {
        g_rowptr[i] = prefix;
        prefix += g_cnt[i];
    }
    if (t == 1023) g_rowptr[n] = sdata[1023];
}

__global__ void csr_scatter(const int* __restrict__ ei,
                            const int* __restrict__ bt,
                            const float* __restrict__ coords,
                            const float* __restrict__ conv_w,
                            const float* __restrict__ conv_b, int E)
{
    int e = blockIdx.x * 256 + threadIdx.x;
    if (e >= E) return;
    int src = ei[e];
    int dst = ei[E + e];
    int pos = g_rowptr[dst] + atomicAdd(&g_cnt2[dst], 1);
    g_perm[pos] = src;
    g_normArr[pos] = conv_w[bt[e]] + conv_b[0];
    float dx = coords[src * 3 + 0] - coords[dst * 3 + 0];
    float dy = coords[src * 3 + 1] - coords[dst * 3 + 1];
    float dz = coords[src * 3 + 2] - coords[dst * 3 + 2];
    g_d2Arr[pos] = dx * dx + dy * dy + dz * dz;
}

// ---------------------------------------------------------------------------
// CSR edge passes: warp per dst node, register accumulation, plain stores.
// ---------------------------------------------------------------------------
__global__ void __launch_bounds__(256) csr_node_struct(
    const float4* __restrict__ Un, const float4* __restrict__ Vn,
    const float4* __restrict__ x,
    float4* __restrict__ Pn, float4* __restrict__ T,
    float* __restrict__ sArr, float* __restrict__ dArr, int n)
{
    int v = blockIdx.x * 8 + (threadIdx.x >> 5);
    if (v >= n) return;
    int lane = threadIdx.x & 31;
    int beg = g_rowptr[v], end = g_rowptr[v + 1];
    float4 u = Un[v * 32 + lane];
    float4 accP = make_float4(0.f, 0.f, 0.f, 0.f);
    float4 accT = make_float4(0.f, 0.f, 0.f, 0.f);
    float ssum = 0.f;
    #pragma unroll 2
    for (int i = beg; i < end; ++i) {
        int s = __ldg(&g_perm[i]);
        float d2 = __ldg(&g_d2Arr[i]);
        float4 w  = Vn[s * 32 + lane];
        float4 xs = x[s * 32 + lane];
        accP.x += mishf(u.x + w.x);
        accP.y += mishf(u.y + w.y);
        accP.z += mishf(u.z + w.z);
        accP.w += mishf(u.w + w.w);
        accT.x += d2 * xs.x; accT.y += d2 * xs.y;
        accT.z += d2 * xs.z; accT.w += d2 * xs.w;
        ssum += d2;
    }
    Pn[v * 32 + lane] = accP;
    T [v * 32 + lane] = accT;
    if (lane == 0) {
        sArr[v] = ssum;
        dArr[v] = (float)(end - beg);
    }
}

__global__ void __launch_bounds__(256) csr_edge(
    const float4* __restrict__ Ue, const float4* __restrict__ Ve,
    const float* __restrict__ b_el,
    float4* __restrict__ Pe, int n)
{
    int v = blockIdx.x * 8 + (threadIdx.x >> 5);
    if (v >= n) return;
    int lane = threadIdx.x & 31;
    int beg = g_rowptr[v], end = g_rowptr[v + 1];
    float4 u = Ue[v * 32 + lane];
    float4 b = ((const float4*)b_el)[lane];
    float4 acc = make_float4(0.f, 0.f, 0.f, 0.f);
    #pragma unroll 2
    for (int i = beg; i < end; ++i) {
        int s = __ldg(&g_perm[i]);
        float nm = __ldg(&g_normArr[i]);
        float4 w = Ve[s * 32 + lane];
        acc.x += mishf(nm * (u.x + w.x) + b.x);
        acc.y += mishf(nm * (u.y + w.y) + b.y);
        acc.z += mishf(nm * (u.z + w.z) + b.z);
        acc.w += mishf(nm * (u.w + w.w) + b.w);
    }
    Pe[v * 32 + lane] = acc;
}

// ---------------------------------------------------------------------------
// Batched / chain-fused mma.sync GEMM (B prefetch pipelined hi/lo).
// ---------------------------------------------------------------------------
struct Job {
    const float* A; const float* A2;
    const float* rowScale; const float* bias;
    const float* biasRowScale; const float* Cadd;
    float* C;
    int w1, w2, actMode, convertA, chainOut;
};
struct JobList { Job j[6]; int count; };

__global__ void __launch_bounds__(256, 2) mma_gemm(JobList jl, int n)
{
    extern __shared__ __nv_bfloat16 sm[];
    const int tid  = threadIdx.x;
    const int wid  = tid >> 5;
    const int lane = tid & 31;
    const int tq = lane >> 2;
    const int tr = lane & 3;
    const int warpM = wid >> 2;     // 0..1
    const int warpN = wid & 3;      // 0..3
    const int rowBase = blockIdx.x * 64;

    const uint32_t smBase  = smem_u32(sm);
    const uint32_t aHiAddr = smBase;
    const uint32_t aLoAddr = smBase + 17408;
    const uint32_t bHiAddr = smBase + 34816;
    const uint32_t bLoAddr = smBase + 69632;

    const uint32_t aoff0 = ((warpM * 32 + (lane & 15)) * WPAD + (lane >> 4) * 8) * 2;
    const uint32_t aoff1 = aoff0 + 16 * WPAD * 2;
    const int bRow = warpN * 32 + ((lane >> 4) << 3) + (lane & 7);
    const uint32_t boff0 = (bRow * WPAD + ((lane >> 3) & 1) * 8) * 2;
    const uint32_t boff1 = boff0 + 16 * WPAD * 2;

    for (int ji = 0; ji < jl.count; ++ji) {
        const Job J = jl.j[ji];

        float acc[2][4][4];
        #pragma unroll
        for (int i = 0; i < 2; ++i)
            #pragma unroll
            for (int j = 0; j < 4; ++j)
                #pragma unroll
                for (int q = 0; q < 4; ++q) acc[i][j][q] = 0.0f;

        const int passes = (J.A2 != nullptr) ? 2 : 1;
        for (int p = 0; p < passes; ++p) {
            const float* Ap  = p ? J.A2 : J.A;
            const float* rsp = p ? nullptr : J.rowScale;
            const bool doConv = (p == 1) || (J.convertA != 0);
            const int  w = p ? J.w2 : J.w1;

            __syncthreads();   // previous mainloop / chain writes done

            // --- B prefetch: hi (group of 9 iters) then lo (8 iters) ---
            {
                const char* src = (const char*)g_wt[w] + tid * 16;
                uint32_t dst = bHiAddr + tid * 16;
                #pragma unroll
                for (int it = 0; it < 9; ++it)
                    cp_async16(dst + it * 4096, src + it * 4096);
                asm volatile("cp.async.commit_group;" ::: "memory");
                #pragma unroll
                for (int it = 9; it < 17; ++it)
                    cp_async16(dst + it * 4096, src + it * 4096);
                asm volatile("cp.async.commit_group;" ::: "memory");
            }

            // --- A tile: 64x128 fp32 -> hi/lo bf16 (overlaps B prefetch) ---
            if (doConv) {
                #pragma unroll
                for (int it = 0; it < 8; ++it) {
                    int idx = tid + (it << 8);
                    int row = idx >> 5;
                    int c4  = idx & 31;
                    int grow = rowBase + row;
                    float4 v = make_float4(0.f, 0.f, 0.f, 0.f);
                    if (grow < n) {
                        v = *(const float4*)&Ap[grow * 128 + c4 * 4];
                        if (rsp) {
                            float s = __ldg(&rsp[grow]);
                            v.x *= s; v.y *= s; v.z *= s; v.w *= s;
                        }
                    }
                    __nv_bfloat16 hx = __float2bfloat16(v.x);
                    __nv_bfloat16 hy = __float2bfloat16(v.y);
                    __nv_bfloat16 hz = __float2bfloat16(v.z);
                    __nv_bfloat16 hw = __float2bfloat16(v.w);
                    __nv_bfloat162 h01; h01.x = hx; h01.y = hy;
                    __nv_bfloat162 h23; h23.x = hz; h23.y = hw;
                    __nv_bfloat162 l01, l23;
                    l01.x = __float2bfloat16(v.x - __bfloat162float(hx));
                    l01.y = __float2bfloat16(v.y - __bfloat162float(hy));
                    l23.x = __float2bfloat16(v.z - __bfloat162float(hz));
                    l23.y = __float2bfloat16(v.w - __bfloat162float(hw));
                    int o = row * WPAD + c4 * 4;
                    *(__nv_bfloat162*)&sm[o]            = h01;
                    *(__nv_bfloat162*)&sm[o + 2]        = h23;
                    *(__nv_bfloat162*)&sm[8704 + o]     = l01;
                    *(__nv_bfloat162*)&sm[8704 + o + 2] = l23;
                }
            }
            // B_hi arrived (1 group still pending: lo)
            asm volatile("cp.async.wait_group 1;" ::: "memory");
            __syncthreads();

            // --- split terms using B_hi: hi_a·hi_b, lo_a·hi_b ---
            #pragma unroll
            for (int sel = 0; sel < 2; ++sel) {
                const uint32_t aB = (sel == 1) ? aLoAddr : aHiAddr;
                #pragma unroll
                for (int kk = 0; kk < 8; ++kk) {
                    uint32_t ko = kk * 32;
                    uint32_t a0[4], a1[4], b0[4], b1[4];
                    ldsm4(a0, aB + aoff0 + ko);
                    ldsm4(a1, aB + aoff1 + ko);
                    ldsm4(b0, bHiAddr + boff0 + ko);
                    ldsm4(b1, bHiAddr + boff1 + ko);
                    mma_bf16(acc[0][0], a0, &b0[0]);
                    mma_bf16(acc[0][1], a0, &b0[2]);
                    mma_bf16(acc[0][2], a0, &b1[0]);
                    mma_bf16(acc[0][3], a0, &b1[2]);
                    mma_bf16(acc[1][0], a1, &b0[0]);
                    mma_bf16(acc[1][1], a1, &b0[2]);
                    mma_bf16(acc[1][2], a1, &b1[0]);
                    mma_bf16(acc[1][3], a1, &b1[2]);
                }
            }
            // B_lo arrived
            asm volatile("cp.async.wait_group 0;" ::: "memory");
            __syncthreads();

            // --- split term hi_a·lo_b ---
            #pragma unroll
            for (int kk = 0; kk < 8; ++kk) {
                uint32_t ko = kk * 32;
                uint32_t a0[4], a1[4], b0[4], b1[4];
                ldsm4(a0, aHiAddr + aoff0 + ko);
                ldsm4(a1, aHiAddr + aoff1 + ko);
                ldsm4(b0, bLoAddr + boff0 + ko);
                ldsm4(b1, bLoAddr + boff1 + ko);
                mma_bf16(acc[0][0], a0, &b0[0]);
                mma_bf16(acc[0][1], a0, &b0[2]);
                mma_bf16(acc[0][2], a0, &b1[0]);
                mma_bf16(acc[0][3], a0, &b1[2]);
                mma_bf16(acc[1][0], a1, &b0[0]);
                mma_bf16(acc[1][1], a1, &b0[2]);
                mma_bf16(acc[1][2], a1, &b1[0]);
                mma_bf16(acc[1][3], a1, &b1[2]);
            }
        }

        if (J.chainOut) {
            __syncthreads();   // all warps done reading A smem
            #pragma unroll
            for (int mt = 0; mt < 2; ++mt) {
                #pragma unroll
                for (int half = 0; half < 2; ++half) {
                    int rloc = warpM * 32 + mt * 16 + tq + half * 8;
                    #pragma unroll
                    for (int nt = 0; nt < 4; ++nt) {
                        int col = warpN * 32 + nt * 8 + tr * 2;
                        float v0 = acc[mt][nt][half * 2];
                        float v1 = acc[mt][nt][half * 2 + 1];
                        if (J.bias) {
                            v0 += __ldg(&J.bias[col]);
                            v1 += __ldg(&J.bias[col + 1]);
                        }
                        if (J.actMode == 1)      { v0 = mishf(v0); v1 = mishf(v1); }
                        else if (J.actMode == 2) { v0 = mishf(mishf(v0)); v1 = mishf(mishf(v1)); }
                        __nv_bfloat16 h0 = __float2bfloat16(v0);
                        __nv_bfloat16 h1 = __float2bfloat16(v1);
                        __nv_bfloat162 hh; hh.x = h0; hh.y = h1;
                        __nv_bfloat162 ll;
                        ll.x = __float2bfloat16(v0 - __bfloat162float(h0));
                        ll.y = __float2bfloat16(v1 - __bfloat162float(h1));
                        int o = rloc * WPAD + col;
                        *(__nv_bfloat162*)&sm[o]        = hh;
                        *(__nv_bfloat162*)&sm[8704 + o] = ll;
                    }
                }
            }
        } else {
            #pragma unroll
            for (int mt = 0; mt < 2; ++mt) {
                #pragma unroll
                for (int half = 0; half < 2; ++half) {
                    int grow = rowBase + warpM * 32 + mt * 16 + tq + half * 8;
                    if (grow >= n) continue;
                    float brs = J.biasRowScale ? __ldg(&J.biasRowScale[grow]) : 1.0f;
                    #pragma unroll
                    for (int nt = 0; nt < 4; ++nt) {
                        int col = warpN * 32 + nt * 8 + tr * 2;
                        float v0 = acc[mt][nt][half * 2];
                        float v1 = acc[mt][nt][half * 2 + 1];
                        if (J.bias) {
                            v0 += __ldg(&J.bias[col])     * brs;
                            v1 += __ldg(&J.bias[col + 1]) * brs;
                        }
                        if (J.Cadd) {
                            float2 ca = *(const float2*)&J.Cadd[grow * 128 + col];
                            v0 += ca.x; v1 += ca.y;
                        }
                        if (J.actMode == 1)      { v0 = mishf(v0); v1 = mishf(v1); }
                        else if (J.actMode == 2) { v0 = mishf(mishf(v0)); v1 = mishf(mishf(v1)); }
                        *(float2*)&J.C[grow * 128 + col] = make_float2(v0, v1);
                    }
                }
            }
        }
    }
}

// ---------------------------------------------------------------------------
__global__ void attention_kernel(
    const float4* __restrict__ e0, const float4* __restrict__ e1,
    const float4* __restrict__ e2,
    const float4* __restrict__ f0, const float4* __restrict__ f1,
    const float4* __restrict__ f2,
    float4* __restrict__ att, int n4)
{
    int i = blockIdx.x * blockDim.x + threadIdx.x;
    if (i >= n4) return;
    float4 a0 = e0[i], a1 = e1[i], a2 = e2[i];
    float4 g0 = f0[i], g1 = f1[i], g2 = f2[i];
    float4 o;
    {
        float m = fmaxf(a0.x, fmaxf(a1.x, a2.x));
        float p0 = __expf(a0.x - m), p1 = __expf(a1.x - m), p2 = __expf(a2.x - m);
        o.x = __fdividef(p0 * g0.x + p1 * g1.x + p2 * g2.x, p0 + p1 + p2);
    }
    {
        float m = fmaxf(a0.y, fmaxf(a1.y, a2.y));
        float p0 = __expf(a0.y - m), p1 = __expf(a1.y - m), p2 = __expf(a2.y - m);
        o.y = __fdividef(p0 * g0.y + p1 * g1.y + p2 * g2.y, p0 + p1 + p2);
    }
    {
        float m = fmaxf(a0.z, fmaxf(a1.z, a2.z));
        float p0 = __expf(a0.z - m), p1 = __expf(a1.z - m), p2 = __expf(a2.z - m);
        o.z = __fdividef(p0 * g0.z + p1 * g1.z + p2 * g2.z, p0 + p1 + p2);
    }
    {
        float m = fmaxf(a0.w, fmaxf(a1.w, a2.w));
        float p0 = __expf(a0.w - m), p1 = __expf(a1.w - m), p2 = __expf(a2.w - m);
        o.w = __fdividef(p0 * g0.w + p1 * g1.w + p2 * g2.w, p0 + p1 + p2);
    }
    att[i] = o;
}

__global__ void bnstat_kernel(const float* __restrict__ H,
                              float* sum, float* sq, int n)
{
    int d  = threadIdx.x;
    int r0 = blockIdx.x * 256;
    int r1 = min(r0 + 256, n);
    float s = 0.f, q = 0.f;
    for (int r = r0; r < r1; ++r) {
        float v = H[r * 128 + d];
        s += v; q += v * v;
    }
    atomicAdd(&sum[d], s);
    atomicAdd(&sq[d],  q);
}

__global__ void final_kernel(const float* __restrict__ H,
                             const float* __restrict__ sum,
                             const float* __restrict__ sq,
                             const float* __restrict__ gamma,
                             const float* __restrict__ beta,
                             float* __restrict__ out, int n)
{
    int i = blockIdx.x * blockDim.x + threadIdx.x;
    if (i >= n * 128) return;
    int d = i & 127;
    float invn = 1.0f / (float)n;
    float mean = sum[d] * invn;
    float var  = sq[d] * invn - mean * mean;
    float v = (H[i] - mean) * rsqrtf(var + 1e-5f) * gamma[d] + beta[d];
    out[i] = mishf(v);
}

// ---------------------------------------------------------------------------
// Host launch
// ---------------------------------------------------------------------------
static float* symaddr(const void* sym) {
    void* p = nullptr;
    cudaGetSymbolAddress(&p, sym);
    return (float*)p;
}

#define GEMM_SMEM 104448

static Job mkjob(const float* A, int w1, float* C, int act,
                 const float* bias = nullptr, int convertA = 1,
                 const float* A2 = nullptr, int w2 = -1,
                 const float* rowScale = nullptr,
                 const float* brs = nullptr, const float* Cadd = nullptr,
                 int chainOut = 0)
{
    Job j;
    j.A = A; j.A2 = A2; j.rowScale = rowScale; j.bias = bias;
    j.biasRowScale = brs; j.Cadd = Cadd; j.C = C;
    j.w1 = w1; j.w2 = w2; j.actMode = act; j.convertA = convertA;
    j.chainOut = chainOut;
    return j;
}

extern "C" void kernel_launch(void* const* d_in, const int* in_sizes, int n_in,
                              void* d_out, int out_size)
{
    const float* x       = (const float*)d_in[0];
    const float* coords  = (const float*)d_in[1];
    const int*   ei      = (const int*)  d_in[2];
    const int*   bt      = (const int*)  d_in[3];
    const float* W_nb    = (const float*)d_in[4];
    const float* b_nb    = (const float*)d_in[5];
    const float* W_nout  = (const float*)d_in[6];
    const float* b_nout  = (const float*)d_in[7];
    const float* conv_w  = (const float*)d_in[8];
    const float* conv_b  = (const float*)d_in[9];
    const float* W_el    = (const float*)d_in[10];
    const float* b_el    = (const float*)d_in[11];
    const float* W_eout  = (const float*)d_in[12];
    const float* b_eout  = (const float*)d_in[13];
    const float* W_coord = (const float*)d_in[14];
    const float* b_coord = (const float*)d_in[15];
    const float* W_pair  = (const float*)d_in[16];
    const float* b_pair  = (const float*)d_in[17];
    const float* W_sout  = (const float*)d_in[18];
    const float* b_sout  = (const float*)d_in[19];
    const float* W_init  = (const float*)d_in[20];
    const float* feat_lin= (const float*)d_in[21];
    const float* W_att   = (const float*)d_in[22];
    const float* W_agg   = (const float*)d_in[23];
    const float* gamma   = (const float*)d_in[24];
    const float* beta    = (const float*)d_in[25];

    const int N = in_sizes[0] / 128;
    const int E = in_sizes[2] / 2;

    static bool attrSet = false;
    if (!attrSet) {
        cudaFuncSetAttribute(mma_gemm,
            cudaFuncAttributeMaxDynamicSharedMemorySize, GEMM_SMEM);
        attrSet = true;
    }

    float* Un    = symaddr(g_b0);
    float* Vn    = symaddr(g_b1);
    float* Ue    = symaddr(g_b2);
    float* Ve    = symaddr(g_b3);
    float* Hagg  = symaddr(g_b4);
    float* Einit = symaddr(g_b5);
    float* Pn    = symaddr(g_b6);
    float* Pe    = symaddr(g_b7);
    float* T     = symaddr(g_b8);
    float* Fn    = symaddr(g_b9);
    float* Fe    = symaddr(g_b10);
    float* Qp    = symaddr(g_b11);
    float* Fs    = symaddr(g_b13);
    float* sArr  = symaddr(g_s);
    float* dArr  = symaddr(g_deg);
    float* bnS   = symaddr(g_bnsum);
    float* bnQ   = symaddr(g_bnsq);
    float* E0 = Un; float* E1 = Vn; float* E2 = Ue;
    float* Att = Ve;

    int* cntP  = (int*)symaddr(g_cnt);
    int* cnt2P = (int*)symaddr(g_cnt2);

    cudaMemsetAsync(cntP,  0, N * sizeof(int));
    cudaMemsetAsync(cnt2P, 0, N * sizeof(int));
    cudaMemsetAsync(bnS, 0, 128 * sizeof(float));
    cudaMemsetAsync(bnQ, 0, 128 * sizeof(float));

    // Weight indices in g_wt:
    //  0 Wnb_top  1 Wnb_bot  2 Wel_top  3 Wel_bot  4 W_init  5 Watt_top
    //  6 W_nout   7 W_eout   8 Wc_top   9 Wc_bot  10 W_pair 11 Ws_top
    // 12 Ws_bot  13 fl0     14 fl1     15 fl2     16 Watt_bot 17 W_agg
    WPtrs wp;
    wp.p[0]  = W_nb;               wp.p[1]  = W_nb + 128 * 128;
    wp.p[2]  = W_el;               wp.p[3]  = W_el + 128 * 128;
    wp.p[4]  = W_init;             wp.p[5]  = W_att;
    wp.p[6]  = W_nout;             wp.p[7]  = W_eout;
    wp.p[8]  = W_coord;            wp.p[9]  = W_coord + 128 * 128;
    wp.p[10] = W_pair;             wp.p[11] = W_sout;
    wp.p[12] = W_sout + 128 * 128; wp.p[13] = feat_lin;
    wp.p[14] = feat_lin + 128 * 128; wp.p[15] = feat_lin + 2 * 128 * 128;
    wp.p[16] = W_att + 128 * 128;  wp.p[17] = W_agg;

    setup_weights<<<dim3(18, 8), 256>>>(wp);

    // --- CSR build (overlaps conceptually with L1 GEMM in issue order) ---
    int egrid = (E + 255) / 256;
    csr_count<<<egrid, 256>>>(ei, E);
    csr_scan<<<1, 1024>>>(N);
    csr_scatter<<<egrid, 256>>>(ei, bt, coords, conv_w, conv_b, E);

    dim3 gb(256);
    dim3 gg((N + 63) / 64);

    JobList jl;

    // --- L1: 4 projections + (Hini chain -> Einit), all sharing A=x ---
    jl.count = 6;
    jl.j[0] = mkjob(x, 0, Un,   0, b_nb, 1);
    jl.j[1] = mkjob(x, 1, Vn,   0, nullptr, 0);
    jl.j[2] = mkjob(x, 2, Ue,   0, nullptr, 0);
    jl.j[3] = mkjob(x, 3, Ve,   0, nullptr, 0);
    jl.j[4] = mkjob(x, 4, nullptr, 2, nullptr, 0, nullptr, -1, nullptr, nullptr, nullptr, 1);
    jl.j[5] = mkjob(x, 5, Einit, 0, nullptr, 0);   // consumes chained Hini
    mma_gemm<<<gg, gb, GEMM_SMEM>>>(jl, N);

    // --- edge phase: 2 CSR passes (no atomics, no memsets) ---
    int ngrid = (N + 7) / 8;
    csr_node_struct<<<ngrid, 256>>>((const float4*)Un, (const float4*)Vn,
                                    (const float4*)x,
                                    (float4*)Pn, (float4*)T, sArr, dArr, N);
    csr_edge<<<ngrid, 256>>>((const float4*)Ue, (const float4*)Ve, b_el,
                             (float4*)Pe, N);

    // --- L3: Fn, Fe, Qp ---
    jl.count = 3;
    jl.j[0] = mkjob(Pn, 6, Fn, 1, b_nout, 1);
    jl.j[1] = mkjob(Pe, 7, Fe, 1, b_eout, 1);
    jl.j[2] = mkjob(x, 8, Qp, 0, b_coord, 1, T, 9, sArr, dArr);
    mma_gemm<<<gg, gb, GEMM_SMEM>>>(jl, N);

    // --- L4: Q chain -> Fs = mish(Q@Ws_bot + x@Ws_top + b_sout) ---
    jl.count = 2;
    jl.j[0] = mkjob(Qp, 10, nullptr, 1, b_pair, 1, nullptr, -1, nullptr, nullptr, nullptr, 1);
    jl.j[1] = mkjob(x, 12, Fs, 1, b_sout, 0, x, 11);
    mma_gemm<<<gg, gb, GEMM_SMEM>>>(jl, N);

    // --- L5: per path, HR chain (mish^2) -> E_f = HR@Watt_bot + Einit ---
    jl.count = 6;
    jl.j[0] = mkjob(Fn, 13, nullptr, 2, nullptr, 1, nullptr, -1, nullptr, nullptr, nullptr, 1);
    jl.j[1] = mkjob(x, 16, E0, 0, nullptr, 0, nullptr, -1, nullptr, nullptr, Einit);
    jl.j[2] = mkjob(Fe, 14, nullptr, 2, nullptr, 1, nullptr, -1, nullptr, nullptr, nullptr, 1);
    jl.j[3] = mkjob(x, 16, E1, 0, nullptr, 0, nullptr, -1, nullptr, nullptr, Einit);
    jl.j[4] = mkjob(Fs, 15, nullptr, 2, nullptr, 1, nullptr, -1, nullptr, nullptr, nullptr, 1);
    jl.j[5] = mkjob(x, 16, E2, 0, nullptr, 0, nullptr, -1, nullptr, nullptr, Einit);
    mma_gemm<<<gg, gb, GEMM_SMEM>>>(jl, N);

    int n4 = N * 32;
    attention_kernel<<<(n4 + 255) / 256, 256>>>(
        (const float4*)E0, (const float4*)E1, (const float4*)E2,
        (const float4*)Fn, (const float4*)Fe, (const float4*)Fs,
        (float4*)Att, n4);

    // --- L6: Hagg = Att @ W_agg ---
    jl.count = 1;
    jl.j[0] = mkjob(Att, 17, Hagg, 0);
    mma_gemm<<<gg, gb, GEMM_SMEM>>>(jl, N);

    bnstat_kernel<<<(N + 255) / 256, 128>>>(Hagg, bnS, bnQ, N);
    final_kernel<<<(N * 128 + 255) / 256, 256>>>(Hagg, bnS, bnQ, gamma, beta,
                                                 (float*)d_out, N);
}

// round 7
// speedup vs baseline: 1.3231x; 1.3231x over previous
#include <cuda_runtime.h>
#include <cuda_bf16.h>
#include <cstdint>

// ---------------------------------------------------------------------------
// MultiPathLayer: N=50000 nodes, E=800000 edges, D=128.
// GEMMs via mma.sync bf16 (split-bf16, fp32 accuracy), ldmatrix, cp.async
// hi/lo pipelined, smem chain-fusion. Edge phase: fused node+edge pass +
// struct pass, vectorized global reductions (warp-per-edge, high MLP).
// ---------------------------------------------------------------------------

#define NMAX 50000
#define DDIM 128
#define WPAD 136           // padded row length in bf16 elems — LDSM conflict-free
#define WELEMS (128 * WPAD)

__device__ float4 g_b0 [NMAX * 32];   // Un   -> later E0
__device__ float4 g_b1 [NMAX * 32];   // Vn   -> later E1
__device__ float4 g_b2 [NMAX * 32];   // Ue   -> later E2
__device__ float4 g_b3 [NMAX * 32];   // Ve   -> later Att
__device__ float4 g_b4 [NMAX * 32];   // Hagg
__device__ float4 g_b5 [NMAX * 32];   // Einit
__device__ float4 g_b6 [NMAX * 32];   // Pn
__device__ float4 g_b7 [NMAX * 32];   // Pe
__device__ float4 g_b8 [NMAX * 32];   // T
__device__ float4 g_b9 [NMAX * 32];   // Fn
__device__ float4 g_b10[NMAX * 32];   // Fe
__device__ float4 g_b11[NMAX * 32];   // Qp
__device__ float4 g_b13[NMAX * 32];   // Fs
__device__ float  g_s[NMAX];
__device__ float  g_deg[NMAX];
__device__ float  g_bnsum[DDIM];
__device__ float  g_bnsq[DDIM];

// Pre-converted weights: [weight][hi/lo][n*WPAD + k] (B operand layout [n][k]).
__device__ __align__(16) __nv_bfloat16 g_wt[18][2][WELEMS];

__device__ __forceinline__ float mishf(float x) {
    float e  = __expf(fminf(x, 30.0f));
    float t  = 1.0f + e;
    float t2 = t * t;
    return x * __fdividef(t2 - 1.0f, t2 + 1.0f);
}

__device__ __forceinline__ void red_add_v4(float4* p, float4 v) {
    asm volatile("red.global.add.v4.f32 [%0], {%1,%2,%3,%4};"
                 :: "l"(p), "f"(v.x), "f"(v.y), "f"(v.z), "f"(v.w)
                 : "memory");
}

__device__ __forceinline__ uint32_t smem_u32(const void* p) {
    uint32_t a;
    asm("{ .reg .u64 t; cvta.to.shared.u64 t, %1; cvt.u32.u64 %0, t; }"
        : "=r"(a) : "l"(p));
    return a;
}

__device__ __forceinline__ void mma_bf16(float* c, const uint32_t* a,
                                         const uint32_t* b) {
    asm volatile(
        "mma.sync.aligned.m16n8k16.row.col.f32.bf16.bf16.f32 "
        "{%0,%1,%2,%3}, {%4,%5,%6,%7}, {%8,%9}, {%0,%1,%2,%3};"
        : "+f"(c[0]), "+f"(c[1]), "+f"(c[2]), "+f"(c[3])
        : "r"(a[0]), "r"(a[1]), "r"(a[2]), "r"(a[3]), "r"(b[0]), "r"(b[1]));
}

__device__ __forceinline__ void ldsm4(uint32_t* r, uint32_t addr) {
    asm volatile("ldmatrix.sync.aligned.m8n8.x4.shared.b16 {%0,%1,%2,%3}, [%4];"
        : "=r"(r[0]), "=r"(r[1]), "=r"(r[2]), "=r"(r[3]) : "r"(addr));
}

__device__ __forceinline__ void cp_async16(uint32_t saddr, const void* g) {
    asm volatile("cp.async.cg.shared.global [%0], [%1], 16;"
                 :: "r"(saddr), "l"(g) : "memory");
}

// ---------------------------------------------------------------------------
// Weight setup.
// ---------------------------------------------------------------------------
struct WPtrs { const float* p[18]; };

__global__ void setup_weights(WPtrs wp)
{
    int w = blockIdx.x;
    const float* W = wp.p[w];
    __nv_bfloat16* hi = g_wt[w][0];
    __nv_bfloat16* lo = g_wt[w][1];
    for (int it = 0; it < 8; ++it) {
        int idx = blockIdx.y * 2048 + it * 256 + threadIdx.x;
        int k = idx >> 7;
        int n = idx & 127;
        float v = W[idx];
        __nv_bfloat16 h = __float2bfloat16(v);
        __nv_bfloat16 l = __float2bfloat16(v - __bfloat162float(h));
        hi[n * WPAD + k] = h;
        lo[n * WPAD + k] = l;
    }
}

// ---------------------------------------------------------------------------
// Edge phase pass 1: fused node+edge paths. One warp per edge, 4 gathers in
// flight, two vectorized reds. Working set ~150MB (mostly L2).
// ---------------------------------------------------------------------------
__global__ void __launch_bounds__(256) edge_ne(
    const int*   __restrict__ ei,
    const int*   __restrict__ bt,
    const float* __restrict__ conv_w,
    const float* __restrict__ conv_b,
    const float* __restrict__ b_el,
    const float4* __restrict__ Un, const float4* __restrict__ Vn,
    const float4* __restrict__ Ue, const float4* __restrict__ Ve,
    float4* Pn, float4* Pe, int E)
{
    int e = blockIdx.x * 8 + (threadIdx.x >> 5);
    if (e >= E) return;
    int lane = threadIdx.x & 31;

    int src = ei[e];
    int dst = ei[E + e];
    float norm = conv_w[bt[e]] + conv_b[0];

    int di = dst * 32 + lane;
    int si = src * 32 + lane;

    // issue all 4 gathers before any compute (MLP=4)
    float4 un = Un[di];
    float4 vn = Vn[si];
    float4 ue = Ue[di];
    float4 ve = Ve[si];
    float4 b  = ((const float4*)b_el)[lane];

    float4 m;
    m.x = mishf(un.x + vn.x); m.y = mishf(un.y + vn.y);
    m.z = mishf(un.z + vn.z); m.w = mishf(un.w + vn.w);
    red_add_v4(&Pn[di], m);

    m.x = mishf(norm * (ue.x + ve.x) + b.x);
    m.y = mishf(norm * (ue.y + ve.y) + b.y);
    m.z = mishf(norm * (ue.z + ve.z) + b.z);
    m.w = mishf(norm * (ue.w + ve.w) + b.w);
    red_add_v4(&Pe[di], m);
}

// ---------------------------------------------------------------------------
// Edge phase pass 2: struct path (x gather + T/s/deg reductions), ~75MB WS.
// ---------------------------------------------------------------------------
__global__ void __launch_bounds__(256) edge_struct(
    const int* __restrict__ ei, const float* __restrict__ coords,
    const float4* __restrict__ x,
    float4* T, float* s_arr, float* deg_arr, int E)
{
    int e = blockIdx.x * 8 + (threadIdx.x >> 5);
    if (e >= E) return;
    int lane = threadIdx.x & 31;
    int src = ei[e];
    int dst = ei[E + e];
    float dx = coords[src * 3 + 0] - coords[dst * 3 + 0];
    float dy = coords[src * 3 + 1] - coords[dst * 3 + 1];
    float dz = coords[src * 3 + 2] - coords[dst * 3 + 2];
    float d2 = dx * dx + dy * dy + dz * dz;
    float4 xs = x[src * 32 + lane];
    float4 m = make_float4(d2 * xs.x, d2 * xs.y, d2 * xs.z, d2 * xs.w);
    red_add_v4(&T[dst * 32 + lane], m);
    if (lane == 0) {
        atomicAdd(&s_arr[dst], d2);
        atomicAdd(&deg_arr[dst], 1.0f);
    }
}

// ---------------------------------------------------------------------------
// Batched / chain-fused mma.sync GEMM (B prefetch pipelined hi/lo).
// ---------------------------------------------------------------------------
struct Job {
    const float* A; const float* A2;
    const float* rowScale; const float* bias;
    const float* biasRowScale; const float* Cadd;
    float* C;
    int w1, w2, actMode, convertA, chainOut;
};
struct JobList { Job j[6]; int count; };

__global__ void __launch_bounds__(256, 2) mma_gemm(JobList jl, int n)
{
    extern __shared__ __nv_bfloat16 sm[];
    const int tid  = threadIdx.x;
    const int wid  = tid >> 5;
    const int lane = tid & 31;
    const int tq = lane >> 2;
    const int tr = lane & 3;
    const int warpM = wid >> 2;     // 0..1
    const int warpN = wid & 3;      // 0..3
    const int rowBase = blockIdx.x * 64;

    const uint32_t smBase  = smem_u32(sm);
    const uint32_t aHiAddr = smBase;
    const uint32_t aLoAddr = smBase + 17408;
    const uint32_t bHiAddr = smBase + 34816;
    const uint32_t bLoAddr = smBase + 69632;

    const uint32_t aoff0 = ((warpM * 32 + (lane & 15)) * WPAD + (lane >> 4) * 8) * 2;
    const uint32_t aoff1 = aoff0 + 16 * WPAD * 2;
    const int bRow = warpN * 32 + ((lane >> 4) << 3) + (lane & 7);
    const uint32_t boff0 = (bRow * WPAD + ((lane >> 3) & 1) * 8) * 2;
    const uint32_t boff1 = boff0 + 16 * WPAD * 2;

    for (int ji = 0; ji < jl.count; ++ji) {
        const Job J = jl.j[ji];

        float acc[2][4][4];
        #pragma unroll
        for (int i = 0; i < 2; ++i)
            #pragma unroll
            for (int j = 0; j < 4; ++j)
                #pragma unroll
                for (int q = 0; q < 4; ++q) acc[i][j][q] = 0.0f;

        const int passes = (J.A2 != nullptr) ? 2 : 1;
        for (int p = 0; p < passes; ++p) {
            const float* Ap  = p ? J.A2 : J.A;
            const float* rsp = p ? nullptr : J.rowScale;
            const bool doConv = (p == 1) || (J.convertA != 0);
            const int  w = p ? J.w2 : J.w1;

            __syncthreads();   // previous mainloop / chain writes done

            // --- B prefetch: hi group (9 iters) then lo group (8 iters) ---
            {
                const char* src = (const char*)g_wt[w] + tid * 16;
                uint32_t dst = bHiAddr + tid * 16;
                #pragma unroll
                for (int it = 0; it < 9; ++it)
                    cp_async16(dst + it * 4096, src + it * 4096);
                asm volatile("cp.async.commit_group;" ::: "memory");
                #pragma unroll
                for (int it = 9; it < 17; ++it)
                    cp_async16(dst + it * 4096, src + it * 4096);
                asm volatile("cp.async.commit_group;" ::: "memory");
            }

            // --- A tile: 64x128 fp32 -> hi/lo bf16 (overlaps B prefetch) ---
            if (doConv) {
                #pragma unroll
                for (int it = 0; it < 8; ++it) {
                    int idx = tid + (it << 8);
                    int row = idx >> 5;
                    int c4  = idx & 31;
                    int grow = rowBase + row;
                    float4 v = make_float4(0.f, 0.f, 0.f, 0.f);
                    if (grow < n) {
                        v = *(const float4*)&Ap[grow * 128 + c4 * 4];
                        if (rsp) {
                            float s = __ldg(&rsp[grow]);
                            v.x *= s; v.y *= s; v.z *= s; v.w *= s;
                        }
                    }
                    __nv_bfloat16 hx = __float2bfloat16(v.x);
                    __nv_bfloat16 hy = __float2bfloat16(v.y);
                    __nv_bfloat16 hz = __float2bfloat16(v.z);
                    __nv_bfloat16 hw = __float2bfloat16(v.w);
                    __nv_bfloat162 h01; h01.x = hx; h01.y = hy;
                    __nv_bfloat162 h23; h23.x = hz; h23.y = hw;
                    __nv_bfloat162 l01, l23;
                    l01.x = __float2bfloat16(v.x - __bfloat162float(hx));
                    l01.y = __float2bfloat16(v.y - __bfloat162float(hy));
                    l23.x = __float2bfloat16(v.z - __bfloat162float(hz));
                    l23.y = __float2bfloat16(v.w - __bfloat162float(hw));
                    int o = row * WPAD + c4 * 4;
                    *(__nv_bfloat162*)&sm[o]            = h01;
                    *(__nv_bfloat162*)&sm[o + 2]        = h23;
                    *(__nv_bfloat162*)&sm[8704 + o]     = l01;
                    *(__nv_bfloat162*)&sm[8704 + o + 2] = l23;
                }
            }
            // B_hi arrived (lo still pending)
            asm volatile("cp.async.wait_group 1;" ::: "memory");
            __syncthreads();

            // --- split terms using B_hi: hi_a·hi_b, lo_a·hi_b ---
            #pragma unroll
            for (int sel = 0; sel < 2; ++sel) {
                const uint32_t aB = (sel == 1) ? aLoAddr : aHiAddr;
                #pragma unroll
                for (int kk = 0; kk < 8; ++kk) {
                    uint32_t ko = kk * 32;
                    uint32_t a0[4], a1[4], b0[4], b1[4];
                    ldsm4(a0, aB + aoff0 + ko);
                    ldsm4(a1, aB + aoff1 + ko);
                    ldsm4(b0, bHiAddr + boff0 + ko);
                    ldsm4(b1, bHiAddr + boff1 + ko);
                    mma_bf16(acc[0][0], a0, &b0[0]);
                    mma_bf16(acc[0][1], a0, &b0[2]);
                    mma_bf16(acc[0][2], a0, &b1[0]);
                    mma_bf16(acc[0][3], a0, &b1[2]);
                    mma_bf16(acc[1][0], a1, &b0[0]);
                    mma_bf16(acc[1][1], a1, &b0[2]);
                    mma_bf16(acc[1][2], a1, &b1[0]);
                    mma_bf16(acc[1][3], a1, &b1[2]);
                }
            }
            // B_lo arrived
            asm volatile("cp.async.wait_group 0;" ::: "memory");
            __syncthreads();

            // --- split term hi_a·lo_b ---
            #pragma unroll
            for (int kk = 0; kk < 8; ++kk) {
                uint32_t ko = kk * 32;
                uint32_t a0[4], a1[4], b0[4], b1[4];
                ldsm4(a0, aHiAddr + aoff0 + ko);
                ldsm4(a1, aHiAddr + aoff1 + ko);
                ldsm4(b0, bLoAddr + boff0 + ko);
                ldsm4(b1, bLoAddr + boff1 + ko);
                mma_bf16(acc[0][0], a0, &b0[0]);
                mma_bf16(acc[0][1], a0, &b0[2]);
                mma_bf16(acc[0][2], a0, &b1[0]);
                mma_bf16(acc[0][3], a0, &b1[2]);
                mma_bf16(acc[1][0], a1, &b0[0]);
                mma_bf16(acc[1][1], a1, &b0[2]);
                mma_bf16(acc[1][2], a1, &b1[0]);
                mma_bf16(acc[1][3], a1, &b1[2]);
            }
        }

        if (J.chainOut) {
            __syncthreads();   // all warps done reading A smem
            #pragma unroll
            for (int mt = 0; mt < 2; ++mt) {
                #pragma unroll
                for (int half = 0; half < 2; ++half) {
                    int rloc = warpM * 32 + mt * 16 + tq + half * 8;
                    #pragma unroll
                    for (int nt = 0; nt < 4; ++nt) {
                        int col = warpN * 32 + nt * 8 + tr * 2;
                        float v0 = acc[mt][nt][half * 2];
                        float v1 = acc[mt][nt][half * 2 + 1];
                        if (J.bias) {
                            v0 += __ldg(&J.bias[col]);
                            v1 += __ldg(&J.bias[col + 1]);
                        }
                        if (J.actMode == 1)      { v0 = mishf(v0); v1 = mishf(v1); }
                        else if (J.actMode == 2) { v0 = mishf(mishf(v0)); v1 = mishf(mishf(v1)); }
                        __nv_bfloat16 h0 = __float2bfloat16(v0);
                        __nv_bfloat16 h1 = __float2bfloat16(v1);
                        __nv_bfloat162 hh; hh.x = h0; hh.y = h1;
                        __nv_bfloat162 ll;
                        ll.x = __float2bfloat16(v0 - __bfloat162float(h0));
                        ll.y = __float2bfloat16(v1 - __bfloat162float(h1));
                        int o = rloc * WPAD + col;
                        *(__nv_bfloat162*)&sm[o]        = hh;
                        *(__nv_bfloat162*)&sm[8704 + o] = ll;
                    }
                }
            }
        } else {
            #pragma unroll
            for (int mt = 0; mt < 2; ++mt) {
                #pragma unroll
                for (int half = 0; half < 2; ++half) {
                    int grow = rowBase + warpM * 32 + mt * 16 + tq + half * 8;
                    if (grow >= n) continue;
                    float brs = J.biasRowScale ? __ldg(&J.biasRowScale[grow]) : 1.0f;
                    #pragma unroll
                    for (int nt = 0; nt < 4; ++nt) {
                        int col = warpN * 32 + nt * 8 + tr * 2;
                        float v0 = acc[mt][nt][half * 2];
                        float v1 = acc[mt][nt][half * 2 + 1];
                        if (J.bias) {
                            v0 += __ldg(&J.bias[col])     * brs;
                            v1 += __ldg(&J.bias[col + 1]) * brs;
                        }
                        if (J.Cadd) {
                            float2 ca = *(const float2*)&J.Cadd[grow * 128 + col];
                            v0 += ca.x; v1 += ca.y;
                        }
                        if (J.actMode == 1)      { v0 = mishf(v0); v1 = mishf(v1); }
                        else if (J.actMode == 2) { v0 = mishf(mishf(v0)); v1 = mishf(mishf(v1)); }
                        *(float2*)&J.C[grow * 128 + col] = make_float2(v0, v1);
                    }
                }
            }
        }
    }
}

// ---------------------------------------------------------------------------
__global__ void attention_kernel(
    const float4* __restrict__ e0, const float4* __restrict__ e1,
    const float4* __restrict__ e2,
    const float4* __restrict__ f0, const float4* __restrict__ f1,
    const float4* __restrict__ f2,
    float4* __restrict__ att, int n4)
{
    int i = blockIdx.x * blockDim.x + threadIdx.x;
    if (i >= n4) return;
    float4 a0 = e0[i], a1 = e1[i], a2 = e2[i];
    float4 g0 = f0[i], g1 = f1[i], g2 = f2[i];
    float4 o;
    {
        float m = fmaxf(a0.x, fmaxf(a1.x, a2.x));
        float p0 = __expf(a0.x - m), p1 = __expf(a1.x - m), p2 = __expf(a2.x - m);
        o.x = __fdividef(p0 * g0.x + p1 * g1.x + p2 * g2.x, p0 + p1 + p2);
    }
    {
        float m = fmaxf(a0.y, fmaxf(a1.y, a2.y));
        float p0 = __expf(a0.y - m), p1 = __expf(a1.y - m), p2 = __expf(a2.y - m);
        o.y = __fdividef(p0 * g0.y + p1 * g1.y + p2 * g2.y, p0 + p1 + p2);
    }
    {
        float m = fmaxf(a0.z, fmaxf(a1.z, a2.z));
        float p0 = __expf(a0.z - m), p1 = __expf(a1.z - m), p2 = __expf(a2.z - m);
        o.z = __fdividef(p0 * g0.z + p1 * g1.z + p2 * g2.z, p0 + p1 + p2);
    }
    {
        float m = fmaxf(a0.w, fmaxf(a1.w, a2.w));
        float p0 = __expf(a0.w - m), p1 = __expf(a1.w - m), p2 = __expf(a2.w - m);
        o.w = __fdividef(p0 * g0.w + p1 * g1.w + p2 * g2.w, p0 + p1 + p2);
    }
    att[i] = o;
}

__global__ void bnstat_kernel(const float* __restrict__ H,
                              float* sum, float* sq, int n)
{
    int d  = threadIdx.x;
    int r0 = blockIdx.x * 256;
    int r1 = min(r0 + 256, n);
    float s = 0.f, q = 0.f;
    for (int r = r0; r < r1; ++r) {
        float v = H[r * 128 + d];
        s += v; q += v * v;
    }
    atomicAdd(&sum[d], s);
    atomicAdd(&sq[d],  q);
}

__global__ void final_kernel(const float* __restrict__ H,
                             const float* __restrict__ sum,
                             const float* __restrict__ sq,
                             const float* __restrict__ gamma,
                             const float* __restrict__ beta,
                             float* __restrict__ out, int n)
{
    int i = blockIdx.x * blockDim.x + threadIdx.x;
    if (i >= n * 128) return;
    int d = i & 127;
    float invn = 1.0f / (float)n;
    float mean = sum[d] * invn;
    float var  = sq[d] * invn - mean * mean;
    float v = (H[i] - mean) * rsqrtf(var + 1e-5f) * gamma[d] + beta[d];
    out[i] = mishf(v);
}

// ---------------------------------------------------------------------------
// Host launch
// ---------------------------------------------------------------------------
static float* symaddr(const void* sym) {
    void* p = nullptr;
    cudaGetSymbolAddress(&p, sym);
    return (float*)p;
}

#define GEMM_SMEM 104448

static Job mkjob(const float* A, int w1, float* C, int act,
                 const float* bias = nullptr, int convertA = 1,
                 const float* A2 = nullptr, int w2 = -1,
                 const float* rowScale = nullptr,
                 const float* brs = nullptr, const float* Cadd = nullptr,
                 int chainOut = 0)
{
    Job j;
    j.A = A; j.A2 = A2; j.rowScale = rowScale; j.bias = bias;
    j.biasRowScale = brs; j.Cadd = Cadd; j.C = C;
    j.w1 = w1; j.w2 = w2; j.actMode = act; j.convertA = convertA;
    j.chainOut = chainOut;
    return j;
}

extern "C" void kernel_launch(void* const* d_in, const int* in_sizes, int n_in,
                              void* d_out, int out_size)
{
    const float* x       = (const float*)d_in[0];
    const float* coords  = (const float*)d_in[1];
    const int*   ei      = (const int*)  d_in[2];
    const int*   bt      = (const int*)  d_in[3];
    const float* W_nb    = (const float*)d_in[4];
    const float* b_nb    = (const float*)d_in[5];
    const float* W_nout  = (const float*)d_in[6];
    const float* b_nout  = (const float*)d_in[7];
    const float* conv_w  = (const float*)d_in[8];
    const float* conv_b  = (const float*)d_in[9];
    const float* W_el    = (const float*)d_in[10];
    const float* b_el    = (const float*)d_in[11];
    const float* W_eout  = (const float*)d_in[12];
    const float* b_eout  = (const float*)d_in[13];
    const float* W_coord = (const float*)d_in[14];
    const float* b_coord = (const float*)d_in[15];
    const float* W_pair  = (const float*)d_in[16];
    const float* b_pair  = (const float*)d_in[17];
    const float* W_sout  = (const float*)d_in[18];
    const float* b_sout  = (const float*)d_in[19];
    const float* W_init  = (const float*)d_in[20];
    const float* feat_lin= (const float*)d_in[21];
    const float* W_att   = (const float*)d_in[22];
    const float* W_agg   = (const float*)d_in[23];
    const float* gamma   = (const float*)d_in[24];
    const float* beta    = (const float*)d_in[25];

    const int N = in_sizes[0] / 128;
    const int E = in_sizes[2] / 2;

    static bool attrSet = false;
    if (!attrSet) {
        cudaFuncSetAttribute(mma_gemm,
            cudaFuncAttributeMaxDynamicSharedMemorySize, GEMM_SMEM);
        attrSet = true;
    }

    float* Un    = symaddr(g_b0);
    float* Vn    = symaddr(g_b1);
    float* Ue    = symaddr(g_b2);
    float* Ve    = symaddr(g_b3);
    float* Hagg  = symaddr(g_b4);
    float* Einit = symaddr(g_b5);
    float* Pn    = symaddr(g_b6);
    float* Pe    = symaddr(g_b7);
    float* T     = symaddr(g_b8);
    float* Fn    = symaddr(g_b9);
    float* Fe    = symaddr(g_b10);
    float* Qp    = symaddr(g_b11);
    float* Fs    = symaddr(g_b13);
    float* sArr  = symaddr(g_s);
    float* dArr  = symaddr(g_deg);
    float* bnS   = symaddr(g_bnsum);
    float* bnQ   = symaddr(g_bnsq);
    float* E0 = Un; float* E1 = Vn; float* E2 = Ue;
    float* Att = Ve;

    const size_t vecBytes = (size_t)N * 128 * sizeof(float);
    cudaMemsetAsync(Pn,  0, vecBytes);
    cudaMemsetAsync(Pe,  0, vecBytes);
    cudaMemsetAsync(T,   0, vecBytes);
    cudaMemsetAsync(sArr, 0, N * sizeof(float));
    cudaMemsetAsync(dArr, 0, N * sizeof(float));
    cudaMemsetAsync(bnS, 0, 128 * sizeof(float));
    cudaMemsetAsync(bnQ, 0, 128 * sizeof(float));

    // Weight indices in g_wt:
    //  0 Wnb_top  1 Wnb_bot  2 Wel_top  3 Wel_bot  4 W_init  5 Watt_top
    //  6 W_nout   7 W_eout   8 Wc_top   9 Wc_bot  10 W_pair 11 Ws_top
    // 12 Ws_bot  13 fl0     14 fl1     15 fl2     16 Watt_bot 17 W_agg
    WPtrs wp;
    wp.p[0]  = W_nb;               wp.p[1]  = W_nb + 128 * 128;
    wp.p[2]  = W_el;               wp.p[3]  = W_el + 128 * 128;
    wp.p[4]  = W_init;             wp.p[5]  = W_att;
    wp.p[6]  = W_nout;             wp.p[7]  = W_eout;
    wp.p[8]  = W_coord;            wp.p[9]  = W_coord + 128 * 128;
    wp.p[10] = W_pair;             wp.p[11] = W_sout;
    wp.p[12] = W_sout + 128 * 128; wp.p[13] = feat_lin;
    wp.p[14] = feat_lin + 128 * 128; wp.p[15] = feat_lin + 2 * 128 * 128;
    wp.p[16] = W_att + 128 * 128;  wp.p[17] = W_agg;

    setup_weights<<<dim3(18, 8), 256>>>(wp);

    dim3 gb(256);
    dim3 gg((N + 63) / 64);

    JobList jl;

    // --- L1: 4 projections + (Hini chain -> Einit), all sharing A=x ---
    jl.count = 6;
    jl.j[0] = mkjob(x, 0, Un,   0, b_nb, 1);
    jl.j[1] = mkjob(x, 1, Vn,   0, nullptr, 0);
    jl.j[2] = mkjob(x, 2, Ue,   0, nullptr, 0);
    jl.j[3] = mkjob(x, 3, Ve,   0, nullptr, 0);
    jl.j[4] = mkjob(x, 4, nullptr, 2, nullptr, 0, nullptr, -1, nullptr, nullptr, nullptr, 1);
    jl.j[5] = mkjob(x, 5, Einit, 0, nullptr, 0);   // consumes chained Hini
    mma_gemm<<<gg, gb, GEMM_SMEM>>>(jl, N);

    // --- edge phase: fused node+edge pass, then struct pass ---
    int egrid = (E + 7) / 8;
    edge_ne<<<egrid, 256>>>(ei, bt, conv_w, conv_b, b_el,
                            (const float4*)Un, (const float4*)Vn,
                            (const float4*)Ue, (const float4*)Ve,
                            (float4*)Pn, (float4*)Pe, E);
    edge_struct<<<egrid, 256>>>(ei, coords, (const float4*)x,
                                (float4*)T, sArr, dArr, E);

    // --- L3: Fn, Fe, Qp ---
    jl.count = 3;
    jl.j[0] = mkjob(Pn, 6, Fn, 1, b_nout, 1);
    jl.j[1] = mkjob(Pe, 7, Fe, 1, b_eout, 1);
    jl.j[2] = mkjob(x, 8, Qp, 0, b_coord, 1, T, 9, sArr, dArr);
    mma_gemm<<<gg, gb, GEMM_SMEM>>>(jl, N);

    // --- L4: Q chain -> Fs = mish(Q@Ws_bot + x@Ws_top + b_sout) ---
    jl.count = 2;
    jl.j[0] = mkjob(Qp, 10, nullptr, 1, b_pair, 1, nullptr, -1, nullptr, nullptr, nullptr, 1);
    jl.j[1] = mkjob(x, 12, Fs, 1, b_sout, 0, x, 11);
    mma_gemm<<<gg, gb, GEMM_SMEM>>>(jl, N);

    // --- L5: per path, HR chain (mish^2) -> E_f = HR@Watt_bot + Einit ---
    jl.count = 6;
    jl.j[0] = mkjob(Fn, 13, nullptr, 2, nullptr, 1, nullptr, -1, nullptr, nullptr, nullptr, 1);
    jl.j[1] = mkjob(x, 16, E0, 0, nullptr, 0, nullptr, -1, nullptr, nullptr, Einit);
    jl.j[2] = mkjob(Fe, 14, nullptr, 2, nullptr, 1, nullptr, -1, nullptr, nullptr, nullptr, 1);
    jl.j[3] = mkjob(x, 16, E1, 0, nullptr, 0, nullptr, -1, nullptr, nullptr, Einit);
    jl.j[4] = mkjob(Fs, 15, nullptr, 2, nullptr, 1, nullptr, -1, nullptr, nullptr, nullptr, 1);
    jl.j[5] = mkjob(x, 16, E2, 0, nullptr, 0, nullptr, -1, nullptr, nullptr, Einit);
    mma_gemm<<<gg, gb, GEMM_SMEM>>>(jl, N);

    int n4 = N * 32;
    attention_kernel<<<(n4 + 255) / 256, 256>>>(
        (const float4*)E0, (const float4*)E1, (const float4*)E2,
        (const float4*)Fn, (const float4*)Fe, (const float4*)Fs,
        (float4*)Att, n4);

    // --- L6: Hagg = Att @ W_agg ---
    jl.count = 1;
    jl.j[0] = mkjob(Att, 17, Hagg, 0);
    mma_gemm<<<gg, gb, GEMM_SMEM>>>(jl, N);

    bnstat_kernel<<<(N + 255) / 256, 128>>>(Hagg, bnS, bnQ, N);
    final_kernel<<<(N * 128 + 255) / 256, 256>>>(Hagg, bnS, bnQ, gamma, beta,
                                                 (float*)d_out, N);
}

// round 8
// speedup vs baseline: 1.3952x; 1.0545x over previous
#include <cuda_runtime.h>
#include <cuda_bf16.h>
#include <cstdint>

// ---------------------------------------------------------------------------
// MultiPathLayer: N=50000 nodes, E=800000 edges, D=128.
// GEMMs via mma.sync bf16 (split-bf16, fp32 accuracy), ldmatrix, cp.async
// hi/lo pipelined, smem chain-fusion. Edge phase: fused node+edge pass
// (2 edges/warp, MLP=8) + struct pass (4 edges/warp, MLP=4), vectorized reds.
// ---------------------------------------------------------------------------

#define NMAX 50000
#define DDIM 128
#define WPAD 136           // padded row length in bf16 elems — LDSM conflict-free
#define WELEMS (128 * WPAD)

__device__ float4 g_b0 [NMAX * 32];   // Un   -> later E0
__device__ float4 g_b1 [NMAX * 32];   // Vn   -> later E1
__device__ float4 g_b2 [NMAX * 32];   // Ue   -> later E2
__device__ float4 g_b3 [NMAX * 32];   // Ve   -> later Att
__device__ float4 g_b4 [NMAX * 32];   // Hagg
__device__ float4 g_b5 [NMAX * 32];   // Einit
__device__ float4 g_b6 [NMAX * 32];   // Pn
__device__ float4 g_b7 [NMAX * 32];   // Pe
__device__ float4 g_b8 [NMAX * 32];   // T
__device__ float4 g_b9 [NMAX * 32];   // Fn
__device__ float4 g_b10[NMAX * 32];   // Fe
__device__ float4 g_b11[NMAX * 32];   // Qp
__device__ float4 g_b13[NMAX * 32];   // Fs
__device__ float  g_s[NMAX];
__device__ float  g_deg[NMAX];
__device__ float  g_bnsum[DDIM];
__device__ float  g_bnsq[DDIM];

// Pre-converted weights: [weight][hi/lo][n*WPAD + k] (B operand layout [n][k]).
__device__ __align__(16) __nv_bfloat16 g_wt[18][2][WELEMS];

__device__ __forceinline__ float mishf(float x) {
    float e  = __expf(fminf(x, 30.0f));
    float t  = 1.0f + e;
    float t2 = t * t;
    return x * __fdividef(t2 - 1.0f, t2 + 1.0f);
}

__device__ __forceinline__ void red_add_v4(float4* p, float4 v) {
    asm volatile("red.global.add.v4.f32 [%0], {%1,%2,%3,%4};"
                 :: "l"(p), "f"(v.x), "f"(v.y), "f"(v.z), "f"(v.w)
                 : "memory");
}

__device__ __forceinline__ uint32_t smem_u32(const void* p) {
    uint32_t a;
    asm("{ .reg .u64 t; cvta.to.shared.u64 t, %1; cvt.u32.u64 %0, t; }"
        : "=r"(a) : "l"(p));
    return a;
}

__device__ __forceinline__ void mma_bf16(float* c, const uint32_t* a,
                                         const uint32_t* b) {
    asm volatile(
        "mma.sync.aligned.m16n8k16.row.col.f32.bf16.bf16.f32 "
        "{%0,%1,%2,%3}, {%4,%5,%6,%7}, {%8,%9}, {%0,%1,%2,%3};"
        : "+f"(c[0]), "+f"(c[1]), "+f"(c[2]), "+f"(c[3])
        : "r"(a[0]), "r"(a[1]), "r"(a[2]), "r"(a[3]), "r"(b[0]), "r"(b[1]));
}

__device__ __forceinline__ void ldsm4(uint32_t* r, uint32_t addr) {
    asm volatile("ldmatrix.sync.aligned.m8n8.x4.shared.b16 {%0,%1,%2,%3}, [%4];"
        : "=r"(r[0]), "=r"(r[1]), "=r"(r[2]), "=r"(r[3]) : "r"(addr));
}

__device__ __forceinline__ void cp_async16(uint32_t saddr, const void* g) {
    asm volatile("cp.async.cg.shared.global [%0], [%1], 16;"
                 :: "r"(saddr), "l"(g) : "memory");
}

// ---------------------------------------------------------------------------
// Weight setup.
// ---------------------------------------------------------------------------
struct WPtrs { const float* p[18]; };

__global__ void setup_weights(WPtrs wp)
{
    int w = blockIdx.x;
    const float* W = wp.p[w];
    __nv_bfloat16* hi = g_wt[w][0];
    __nv_bfloat16* lo = g_wt[w][1];
    for (int it = 0; it < 8; ++it) {
        int idx = blockIdx.y * 2048 + it * 256 + threadIdx.x;
        int k = idx >> 7;
        int n = idx & 127;
        float v = W[idx];
        __nv_bfloat16 h = __float2bfloat16(v);
        __nv_bfloat16 l = __float2bfloat16(v - __bfloat162float(h));
        hi[n * WPAD + k] = h;
        lo[n * WPAD + k] = l;
    }
}

// ---------------------------------------------------------------------------
// Edge pass 1: fused node+edge paths, 2 edges per warp (8 gathers in flight).
// ---------------------------------------------------------------------------
__global__ void __launch_bounds__(256) edge_ne(
    const int*   __restrict__ ei,
    const int*   __restrict__ bt,
    const float* __restrict__ conv_w,
    const float* __restrict__ conv_b,
    const float* __restrict__ b_el,
    const float4* __restrict__ Un, const float4* __restrict__ Vn,
    const float4* __restrict__ Ue, const float4* __restrict__ Ve,
    float4* Pn, float4* Pe, int E)
{
    int base = (blockIdx.x * 8 + (threadIdx.x >> 5)) * 2;
    if (base >= E) return;
    int lane = threadIdx.x & 31;
    int e1ok = (base + 1 < E);

    int src0 = ei[base];
    int dst0 = ei[E + base];
    int src1 = e1ok ? ei[base + 1]     : src0;
    int dst1 = e1ok ? ei[E + base + 1] : dst0;
    float norm0 = conv_w[bt[base]] + conv_b[0];
    float norm1 = conv_w[bt[e1ok ? base + 1 : base]] + conv_b[0];

    int di0 = dst0 * 32 + lane, si0 = src0 * 32 + lane;
    int di1 = dst1 * 32 + lane, si1 = src1 * 32 + lane;

    // issue all 8 gathers before any compute
    float4 un0 = Un[di0];
    float4 vn0 = Vn[si0];
    float4 ue0 = Ue[di0];
    float4 ve0 = Ve[si0];
    float4 un1 = Un[di1];
    float4 vn1 = Vn[si1];
    float4 ue1 = Ue[di1];
    float4 ve1 = Ve[si1];
    float4 b   = ((const float4*)b_el)[lane];

    float4 m;
    m.x = mishf(un0.x + vn0.x); m.y = mishf(un0.y + vn0.y);
    m.z = mishf(un0.z + vn0.z); m.w = mishf(un0.w + vn0.w);
    red_add_v4(&Pn[di0], m);

    m.x = mishf(norm0 * (ue0.x + ve0.x) + b.x);
    m.y = mishf(norm0 * (ue0.y + ve0.y) + b.y);
    m.z = mishf(norm0 * (ue0.z + ve0.z) + b.z);
    m.w = mishf(norm0 * (ue0.w + ve0.w) + b.w);
    red_add_v4(&Pe[di0], m);

    if (e1ok) {
        m.x = mishf(un1.x + vn1.x); m.y = mishf(un1.y + vn1.y);
        m.z = mishf(un1.z + vn1.z); m.w = mishf(un1.w + vn1.w);
        red_add_v4(&Pn[di1], m);

        m.x = mishf(norm1 * (ue1.x + ve1.x) + b.x);
        m.y = mishf(norm1 * (ue1.y + ve1.y) + b.y);
        m.z = mishf(norm1 * (ue1.z + ve1.z) + b.z);
        m.w = mishf(norm1 * (ue1.w + ve1.w) + b.w);
        red_add_v4(&Pe[di1], m);
    }
}

// ---------------------------------------------------------------------------
// Edge pass 2: struct path, 4 edges per warp (4 x-gathers in flight).
// ---------------------------------------------------------------------------
__global__ void __launch_bounds__(256) edge_struct(
    const int* __restrict__ ei, const float* __restrict__ coords,
    const float4* __restrict__ x,
    float4* T, float* s_arr, float* deg_arr, int E)
{
    int base = (blockIdx.x * 8 + (threadIdx.x >> 5)) * 4;
    if (base >= E) return;
    int lane = threadIdx.x & 31;
    int cnt = min(4, E - base);

    int src[4], dst[4];
    float d2[4];
    #pragma unroll
    for (int q = 0; q < 4; ++q) {
        int e = base + ((q < cnt) ? q : 0);
        src[q] = ei[e];
        dst[q] = ei[E + e];
    }
    #pragma unroll
    for (int q = 0; q < 4; ++q) {
        float dx = coords[src[q] * 3 + 0] - coords[dst[q] * 3 + 0];
        float dy = coords[src[q] * 3 + 1] - coords[dst[q] * 3 + 1];
        float dz = coords[src[q] * 3 + 2] - coords[dst[q] * 3 + 2];
        d2[q] = dx * dx + dy * dy + dz * dz;
    }
    // issue all gathers
    float4 xs[4];
    #pragma unroll
    for (int q = 0; q < 4; ++q)
        xs[q] = x[src[q] * 32 + lane];

    #pragma unroll
    for (int q = 0; q < 4; ++q) {
        if (q >= cnt) break;
        float4 m = make_float4(d2[q] * xs[q].x, d2[q] * xs[q].y,
                               d2[q] * xs[q].z, d2[q] * xs[q].w);
        red_add_v4(&T[dst[q] * 32 + lane], m);
        if (lane == 0) {
            atomicAdd(&s_arr[dst[q]], d2[q]);
            atomicAdd(&deg_arr[dst[q]], 1.0f);
        }
    }
}

// ---------------------------------------------------------------------------
// Batched / chain-fused mma.sync GEMM (B prefetch pipelined hi/lo).
// ---------------------------------------------------------------------------
struct Job {
    const float* A; const float* A2;
    const float* rowScale; const float* bias;
    const float* biasRowScale; const float* Cadd;
    float* C;
    int w1, w2, actMode, convertA, chainOut;
};
struct JobList { Job j[6]; int count; };

__global__ void __launch_bounds__(256, 2) mma_gemm(JobList jl, int n)
{
    extern __shared__ __nv_bfloat16 sm[];
    const int tid  = threadIdx.x;
    const int wid  = tid >> 5;
    const int lane = tid & 31;
    const int tq = lane >> 2;
    const int tr = lane & 3;
    const int warpM = wid >> 2;     // 0..1
    const int warpN = wid & 3;      // 0..3
    const int rowBase = blockIdx.x * 64;

    const uint32_t smBase  = smem_u32(sm);
    const uint32_t aHiAddr = smBase;
    const uint32_t aLoAddr = smBase + 17408;
    const uint32_t bHiAddr = smBase + 34816;
    const uint32_t bLoAddr = smBase + 69632;

    const uint32_t aoff0 = ((warpM * 32 + (lane & 15)) * WPAD + (lane >> 4) * 8) * 2;
    const uint32_t aoff1 = aoff0 + 16 * WPAD * 2;
    const int bRow = warpN * 32 + ((lane >> 4) << 3) + (lane & 7);
    const uint32_t boff0 = (bRow * WPAD + ((lane >> 3) & 1) * 8) * 2;
    const uint32_t boff1 = boff0 + 16 * WPAD * 2;

    for (int ji = 0; ji < jl.count; ++ji) {
        const Job J = jl.j[ji];

        float acc[2][4][4];
        #pragma unroll
        for (int i = 0; i < 2; ++i)
            #pragma unroll
            for (int j = 0; j < 4; ++j)
                #pragma unroll
                for (int q = 0; q < 4; ++q) acc[i][j][q] = 0.0f;

        const int passes = (J.A2 != nullptr) ? 2 : 1;
        for (int p = 0; p < passes; ++p) {
            const float* Ap  = p ? J.A2 : J.A;
            const float* rsp = p ? nullptr : J.rowScale;
            const bool doConv = (p == 1) || (J.convertA != 0);
            const int  w = p ? J.w2 : J.w1;

            __syncthreads();   // previous mainloop / chain writes done

            // --- B prefetch: hi group (9 iters) then lo group (8 iters) ---
            {
                const char* src = (const char*)g_wt[w] + tid * 16;
                uint32_t dst = bHiAddr + tid * 16;
                #pragma unroll
                for (int it = 0; it < 9; ++it)
                    cp_async16(dst + it * 4096, src + it * 4096);
                asm volatile("cp.async.commit_group;" ::: "memory");
                #pragma unroll
                for (int it = 9; it < 17; ++it)
                    cp_async16(dst + it * 4096, src + it * 4096);
                asm volatile("cp.async.commit_group;" ::: "memory");
            }

            // --- A tile: 64x128 fp32 -> hi/lo bf16 (overlaps B prefetch) ---
            if (doConv) {
                #pragma unroll
                for (int it = 0; it < 8; ++it) {
                    int idx = tid + (it << 8);
                    int row = idx >> 5;
                    int c4  = idx & 31;
                    int grow = rowBase + row;
                    float4 v = make_float4(0.f, 0.f, 0.f, 0.f);
                    if (grow < n) {
                        v = *(const float4*)&Ap[grow * 128 + c4 * 4];
                        if (rsp) {
                            float s = __ldg(&rsp[grow]);
                            v.x *= s; v.y *= s; v.z *= s; v.w *= s;
                        }
                    }
                    __nv_bfloat16 hx = __float2bfloat16(v.x);
                    __nv_bfloat16 hy = __float2bfloat16(v.y);
                    __nv_bfloat16 hz = __float2bfloat16(v.z);
                    __nv_bfloat16 hw = __float2bfloat16(v.w);
                    __nv_bfloat162 h01; h01.x = hx; h01.y = hy;
                    __nv_bfloat162 h23; h23.x = hz; h23.y = hw;
                    __nv_bfloat162 l01, l23;
                    l01.x = __float2bfloat16(v.x - __bfloat162float(hx));
                    l01.y = __float2bfloat16(v.y - __bfloat162float(hy));
                    l23.x = __float2bfloat16(v.z - __bfloat162float(hz));
                    l23.y = __float2bfloat16(v.w - __bfloat162float(hw));
                    int o = row * WPAD + c4 * 4;
                    *(__nv_bfloat162*)&sm[o]            = h01;
                    *(__nv_bfloat162*)&sm[o + 2]        = h23;
                    *(__nv_bfloat162*)&sm[8704 + o]     = l01;
                    *(__nv_bfloat162*)&sm[8704 + o + 2] = l23;
                }
            }
            // B_hi arrived (lo still pending)
            asm volatile("cp.async.wait_group 1;" ::: "memory");
            __syncthreads();

            // --- split terms using B_hi: hi_a·hi_b, lo_a·hi_b ---
            #pragma unroll
            for (int sel = 0; sel < 2; ++sel) {
                const uint32_t aB = (sel == 1) ? aLoAddr : aHiAddr;
                #pragma unroll
                for (int kk = 0; kk < 8; ++kk) {
                    uint32_t ko = kk * 32;
                    uint32_t a0[4], a1[4], b0[4], b1[4];
                    ldsm4(a0, aB + aoff0 + ko);
                    ldsm4(a1, aB + aoff1 + ko);
                    ldsm4(b0, bHiAddr + boff0 + ko);
                    ldsm4(b1, bHiAddr + boff1 + ko);
                    mma_bf16(acc[0][0], a0, &b0[0]);
                    mma_bf16(acc[0][1], a0, &b0[2]);
                    mma_bf16(acc[0][2], a0, &b1[0]);
                    mma_bf16(acc[0][3], a0, &b1[2]);
                    mma_bf16(acc[1][0], a1, &b0[0]);
                    mma_bf16(acc[1][1], a1, &b0[2]);
                    mma_bf16(acc[1][2], a1, &b1[0]);
                    mma_bf16(acc[1][3], a1, &b1[2]);
                }
            }
            // B_lo arrived
            asm volatile("cp.async.wait_group 0;" ::: "memory");
            __syncthreads();

            // --- split term hi_a·lo_b ---
            #pragma unroll
            for (int kk = 0; kk < 8; ++kk) {
                uint32_t ko = kk * 32;
                uint32_t a0[4], a1[4], b0[4], b1[4];
                ldsm4(a0, aHiAddr + aoff0 + ko);
                ldsm4(a1, aHiAddr + aoff1 + ko);
                ldsm4(b0, bLoAddr + boff0 + ko);
                ldsm4(b1, bLoAddr + boff1 + ko);
                mma_bf16(acc[0][0], a0, &b0[0]);
                mma_bf16(acc[0][1], a0, &b0[2]);
                mma_bf16(acc[0][2], a0, &b1[0]);
                mma_bf16(acc[0][3], a0, &b1[2]);
                mma_bf16(acc[1][0], a1, &b0[0]);
                mma_bf16(acc[1][1], a1, &b0[2]);
                mma_bf16(acc[1][2], a1, &b1[0]);
                mma_bf16(acc[1][3], a1, &b1[2]);
            }
        }

        if (J.chainOut) {
            __syncthreads();   // all warps done reading A smem
            #pragma unroll
            for (int mt = 0; mt < 2; ++mt) {
                #pragma unroll
                for (int half = 0; half < 2; ++half) {
                    int rloc = warpM * 32 + mt * 16 + tq + half * 8;
                    #pragma unroll
                    for (int nt = 0; nt < 4; ++nt) {
                        int col = warpN * 32 + nt * 8 + tr * 2;
                        float v0 = acc[mt][nt][half * 2];
                        float v1 = acc[mt][nt][half * 2 + 1];
                        if (J.bias) {
                            v0 += __ldg(&J.bias[col]);
                            v1 += __ldg(&J.bias[col + 1]);
                        }
                        if (J.actMode == 1)      { v0 = mishf(v0); v1 = mishf(v1); }
                        else if (J.actMode == 2) { v0 = mishf(mishf(v0)); v1 = mishf(mishf(v1)); }
                        __nv_bfloat16 h0 = __float2bfloat16(v0);
                        __nv_bfloat16 h1 = __float2bfloat16(v1);
                        __nv_bfloat162 hh; hh.x = h0; hh.y = h1;
                        __nv_bfloat162 ll;
                        ll.x = __float2bfloat16(v0 - __bfloat162float(h0));
                        ll.y = __float2bfloat16(v1 - __bfloat162float(h1));
                        int o = rloc * WPAD + col;
                        *(__nv_bfloat162*)&sm[o]        = hh;
                        *(__nv_bfloat162*)&sm[8704 + o] = ll;
                    }
                }
            }
        } else {
            #pragma unroll
            for (int mt = 0; mt < 2; ++mt) {
                #pragma unroll
                for (int half = 0; half < 2; ++half) {
                    int grow = rowBase + warpM * 32 + mt * 16 + tq + half * 8;
                    if (grow >= n) continue;
                    float brs = J.biasRowScale ? __ldg(&J.biasRowScale[grow]) : 1.0f;
                    #pragma unroll
                    for (int nt = 0; nt < 4; ++nt) {
                        int col = warpN * 32 + nt * 8 + tr * 2;
                        float v0 = acc[mt][nt][half * 2];
                        float v1 = acc[mt][nt][half * 2 + 1];
                        if (J.bias) {
                            v0 += __ldg(&J.bias[col])     * brs;
                            v1 += __ldg(&J.bias[col + 1]) * brs;
                        }
                        if (J.Cadd) {
                            float2 ca = *(const float2*)&J.Cadd[grow * 128 + col];
                            v0 += ca.x; v1 += ca.y;
                        }
                        if (J.actMode == 1)      { v0 = mishf(v0); v1 = mishf(v1); }
                        else if (J.actMode == 2) { v0 = mishf(mishf(v0)); v1 = mishf(mishf(v1)); }
                        *(float2*)&J.C[grow * 128 + col] = make_float2(v0, v1);
                    }
                }
            }
        }
    }
}

// ---------------------------------------------------------------------------
__global__ void attention_kernel(
    const float4* __restrict__ e0, const float4* __restrict__ e1,
    const float4* __restrict__ e2,
    const float4* __restrict__ f0, const float4* __restrict__ f1,
    const float4* __restrict__ f2,
    float4* __restrict__ att, int n4)
{
    int i = blockIdx.x * blockDim.x + threadIdx.x;
    if (i >= n4) return;
    float4 a0 = e0[i], a1 = e1[i], a2 = e2[i];
    float4 g0 = f0[i], g1 = f1[i], g2 = f2[i];
    float4 o;
    {
        float m = fmaxf(a0.x, fmaxf(a1.x, a2.x));
        float p0 = __expf(a0.x - m), p1 = __expf(a1.x - m), p2 = __expf(a2.x - m);
        o.x = __fdividef(p0 * g0.x + p1 * g1.x + p2 * g2.x, p0 + p1 + p2);
    }
    {
        float m = fmaxf(a0.y, fmaxf(a1.y, a2.y));
        float p0 = __expf(a0.y - m), p1 = __expf(a1.y - m), p2 = __expf(a2.y - m);
        o.y = __fdividef(p0 * g0.y + p1 * g1.y + p2 * g2.y, p0 + p1 + p2);
    }
    {
        float m = fmaxf(a0.z, fmaxf(a1.z, a2.z));
        float p0 = __expf(a0.z - m), p1 = __expf(a1.z - m), p2 = __expf(a2.z - m);
        o.z = __fdividef(p0 * g0.z + p1 * g1.z + p2 * g2.z, p0 + p1 + p2);
    }
    {
        float m = fmaxf(a0.w, fmaxf(a1.w, a2.w));
        float p0 = __expf(a0.w - m), p1 = __expf(a1.w - m), p2 = __expf(a2.w - m);
        o.w = __fdividef(p0 * g0.w + p1 * g1.w + p2 * g2.w, p0 + p1 + p2);
    }
    att[i] = o;
}

__global__ void bnstat_kernel(const float* __restrict__ H,
                              float* sum, float* sq, int n)
{
    int d  = threadIdx.x;
    int r0 = blockIdx.x * 256;
    int r1 = min(r0 + 256, n);
    float s = 0.f, q = 0.f;
    for (int r = r0; r < r1; ++r) {
        float v = H[r * 128 + d];
        s += v; q += v * v;
    }
    atomicAdd(&sum[d], s);
    atomicAdd(&sq[d],  q);
}

__global__ void final_kernel(const float* __restrict__ H,
                             const float* __restrict__ sum,
                             const float* __restrict__ sq,
                             const float* __restrict__ gamma,
                             const float* __restrict__ beta,
                             float* __restrict__ out, int n)
{
    int i = blockIdx.x * blockDim.x + threadIdx.x;
    if (i >= n * 128) return;
    int d = i & 127;
    float invn = 1.0f / (float)n;
    float mean = sum[d] * invn;
    float var  = sq[d] * invn - mean * mean;
    float v = (H[i] - mean) * rsqrtf(var + 1e-5f) * gamma[d] + beta[d];
    out[i] = mishf(v);
}

// ---------------------------------------------------------------------------
// Host launch
// ---------------------------------------------------------------------------
static float* symaddr(const void* sym) {
    void* p = nullptr;
    cudaGetSymbolAddress(&p, sym);
    return (float*)p;
}

#define GEMM_SMEM 104448

static Job mkjob(const float* A, int w1, float* C, int act,
                 const float* bias = nullptr, int convertA = 1,
                 const float* A2 = nullptr, int w2 = -1,
                 const float* rowScale = nullptr,
                 const float* brs = nullptr, const float* Cadd = nullptr,
                 int chainOut = 0)
{
    Job j;
    j.A = A; j.A2 = A2; j.rowScale = rowScale; j.bias = bias;
    j.biasRowScale = brs; j.Cadd = Cadd; j.C = C;
    j.w1 = w1; j.w2 = w2; j.actMode = act; j.convertA = convertA;
    j.chainOut = chainOut;
    return j;
}

extern "C" void kernel_launch(void* const* d_in, const int* in_sizes, int n_in,
                              void* d_out, int out_size)
{
    const float* x       = (const float*)d_in[0];
    const float* coords  = (const float*)d_in[1];
    const int*   ei      = (const int*)  d_in[2];
    const int*   bt      = (const int*)  d_in[3];
    const float* W_nb    = (const float*)d_in[4];
    const float* b_nb    = (const float*)d_in[5];
    const float* W_nout  = (const float*)d_in[6];
    const float* b_nout  = (const float*)d_in[7];
    const float* conv_w  = (const float*)d_in[8];
    const float* conv_b  = (const float*)d_in[9];
    const float* W_el    = (const float*)d_in[10];
    const float* b_el    = (const float*)d_in[11];
    const float* W_eout  = (const float*)d_in[12];
    const float* b_eout  = (const float*)d_in[13];
    const float* W_coord = (const float*)d_in[14];
    const float* b_coord = (const float*)d_in[15];
    const float* W_pair  = (const float*)d_in[16];
    const float* b_pair  = (const float*)d_in[17];
    const float* W_sout  = (const float*)d_in[18];
    const float* b_sout  = (const float*)d_in[19];
    const float* W_init  = (const float*)d_in[20];
    const float* feat_lin= (const float*)d_in[21];
    const float* W_att   = (const float*)d_in[22];
    const float* W_agg   = (const float*)d_in[23];
    const float* gamma   = (const float*)d_in[24];
    const float* beta    = (const float*)d_in[25];

    const int N = in_sizes[0] / 128;
    const int E = in_sizes[2] / 2;

    static bool attrSet = false;
    if (!attrSet) {
        cudaFuncSetAttribute(mma_gemm,
            cudaFuncAttributeMaxDynamicSharedMemorySize, GEMM_SMEM);
        attrSet = true;
    }

    float* Un    = symaddr(g_b0);
    float* Vn    = symaddr(g_b1);
    float* Ue    = symaddr(g_b2);
    float* Ve    = symaddr(g_b3);
    float* Hagg  = symaddr(g_b4);
    float* Einit = symaddr(g_b5);
    float* Pn    = symaddr(g_b6);
    float* Pe    = symaddr(g_b7);
    float* T     = symaddr(g_b8);
    float* Fn    = symaddr(g_b9);
    float* Fe    = symaddr(g_b10);
    float* Qp    = symaddr(g_b11);
    float* Fs    = symaddr(g_b13);
    float* sArr  = symaddr(g_s);
    float* dArr  = symaddr(g_deg);
    float* bnS   = symaddr(g_bnsum);
    float* bnQ   = symaddr(g_bnsq);
    float* E0 = Un; float* E1 = Vn; float* E2 = Ue;
    float* Att = Ve;

    const size_t vecBytes = (size_t)N * 128 * sizeof(float);
    cudaMemsetAsync(Pn,  0, vecBytes);
    cudaMemsetAsync(Pe,  0, vecBytes);
    cudaMemsetAsync(T,   0, vecBytes);
    cudaMemsetAsync(sArr, 0, N * sizeof(float));
    cudaMemsetAsync(dArr, 0, N * sizeof(float));
    cudaMemsetAsync(bnS, 0, 128 * sizeof(float));
    cudaMemsetAsync(bnQ, 0, 128 * sizeof(float));

    // Weight indices in g_wt:
    //  0 Wnb_top  1 Wnb_bot  2 Wel_top  3 Wel_bot  4 W_init  5 Watt_top
    //  6 W_nout   7 W_eout   8 Wc_top   9 Wc_bot  10 W_pair 11 Ws_top
    // 12 Ws_bot  13 fl0     14 fl1     15 fl2     16 Watt_bot 17 W_agg
    WPtrs wp;
    wp.p[0]  = W_nb;               wp.p[1]  = W_nb + 128 * 128;
    wp.p[2]  = W_el;               wp.p[3]  = W_el + 128 * 128;
    wp.p[4]  = W_init;             wp.p[5]  = W_att;
    wp.p[6]  = W_nout;             wp.p[7]  = W_eout;
    wp.p[8]  = W_coord;            wp.p[9]  = W_coord + 128 * 128;
    wp.p[10] = W_pair;             wp.p[11] = W_sout;
    wp.p[12] = W_sout + 128 * 128; wp.p[13] = feat_lin;
    wp.p[14] = feat_lin + 128 * 128; wp.p[15] = feat_lin + 2 * 128 * 128;
    wp.p[16] = W_att + 128 * 128;  wp.p[17] = W_agg;

    setup_weights<<<dim3(18, 8), 256>>>(wp);

    dim3 gb(256);
    dim3 gg((N + 63) / 64);

    JobList jl;

    // --- L1: 4 projections + (Hini chain -> Einit), all sharing A=x ---
    jl.count = 6;
    jl.j[0] = mkjob(x, 0, Un,   0, b_nb, 1);
    jl.j[1] = mkjob(x, 1, Vn,   0, nullptr, 0);
    jl.j[2] = mkjob(x, 2, Ue,   0, nullptr, 0);
    jl.j[3] = mkjob(x, 3, Ve,   0, nullptr, 0);
    jl.j[4] = mkjob(x, 4, nullptr, 2, nullptr, 0, nullptr, -1, nullptr, nullptr, nullptr, 1);
    jl.j[5] = mkjob(x, 5, Einit, 0, nullptr, 0);   // consumes chained Hini
    mma_gemm<<<gg, gb, GEMM_SMEM>>>(jl, N);

    // --- edge phase: fused node+edge pass (2 e/warp), struct pass (4 e/warp) ---
    edge_ne<<<(E + 15) / 16, 256>>>(ei, bt, conv_w, conv_b, b_el,
                                    (const float4*)Un, (const float4*)Vn,
                                    (const float4*)Ue, (const float4*)Ve,
                                    (float4*)Pn, (float4*)Pe, E);
    edge_struct<<<(E + 31) / 32, 256>>>(ei, coords, (const float4*)x,
                                        (float4*)T, sArr, dArr, E);

    // --- L3: Fn, Fe, Qp ---
    jl.count = 3;
    jl.j[0] = mkjob(Pn, 6, Fn, 1, b_nout, 1);
    jl.j[1] = mkjob(Pe, 7, Fe, 1, b_eout, 1);
    jl.j[2] = mkjob(x, 8, Qp, 0, b_coord, 1, T, 9, sArr, dArr);
    mma_gemm<<<gg, gb, GEMM_SMEM>>>(jl, N);

    // --- L4: Q chain -> Fs = mish(Q@Ws_bot + x@Ws_top + b_sout) ---
    jl.count = 2;
    jl.j[0] = mkjob(Qp, 10, nullptr, 1, b_pair, 1, nullptr, -1, nullptr, nullptr, nullptr, 1);
    jl.j[1] = mkjob(x, 12, Fs, 1, b_sout, 0, x, 11);
    mma_gemm<<<gg, gb, GEMM_SMEM>>>(jl, N);

    // --- L5: per path, HR chain (mish^2) -> E_f = HR@Watt_bot + Einit ---
    jl.count = 6;
    jl.j[0] = mkjob(Fn, 13, nullptr, 2, nullptr, 1, nullptr, -1, nullptr, nullptr, nullptr, 1);
    jl.j[1] = mkjob(x, 16, E0, 0, nullptr, 0, nullptr, -1, nullptr, nullptr, Einit);
    jl.j[2] = mkjob(Fe, 14, nullptr, 2, nullptr, 1, nullptr, -1, nullptr, nullptr, nullptr, 1);
    jl.j[3] = mkjob(x, 16, E1, 0, nullptr, 0, nullptr, -1, nullptr, nullptr, Einit);
    jl.j[4] = mkjob(Fs, 15, nullptr, 2, nullptr, 1, nullptr, -1, nullptr, nullptr, nullptr, 1);
    jl.j[5] = mkjob(x, 16, E2, 0, nullptr, 0, nullptr, -1, nullptr, nullptr, Einit);
    mma_gemm<<<gg, gb, GEMM_SMEM>>>(jl, N);

    int n4 = N * 32;
    attention_kernel<<<(n4 + 255) / 256, 256>>>(
        (const float4*)E0, (const float4*)E1, (const float4*)E2,
        (const float4*)Fn, (const float4*)Fe, (const float4*)Fs,
        (float4*)Att, n4);

    // --- L6: Hagg = Att @ W_agg ---
    jl.count = 1;
    jl.j[0] = mkjob(Att, 17, Hagg, 0);
    mma_gemm<<<gg, gb, GEMM_SMEM>>>(jl, N);

    bnstat_kernel<<<(N + 255) / 256, 128>>>(Hagg, bnS, bnQ, N);
    final_kernel<<<(N * 128 + 255) / 256, 256>>>(Hagg, bnS, bnQ, gamma, beta,
                                                 (float*)d_out, N);
}